// round 1
// baseline (speedup 1.0000x reference)
#include <cuda_runtime.h>

// Problem constants
#define N_SAMPLES 65536
#define EMB       1536
#define HALF      768        // EMB/2: e<HALF depends on idx2 (w); e>=HALF on idx1 (h)
#define BINS      257
#define PLANE     (BINS * BINS)   // 66049, stride between e-slices of pos_embeddings
#define ROW_F4    (EMB / 4)       // 384 float4 per output row
#define HALF_F4   (HALF / 4)      // 192

// 1D factored table, transposed: T[p][e] = pe_value(e, p) + learnable_constant[e].
// 257 * 1536 * 4 B = 1.58 MB -> L2 resident. Static __device__ scratch (no allocs).
__device__ float g_table[BINS * EMB];

// ---------------------------------------------------------------------------
// Kernel A: build the factored table straight from the input pos_embeddings
// (bit-exact with the reference values) with the bias baked in.
//   e < HALF : pe[e, h, w] independent of h  -> read pe[e, 0, p]
//   e >= HALF: pe[e, h, w] independent of w  -> read pe[e, p, 0]
// ---------------------------------------------------------------------------
__global__ void build_table_kernel(const float* __restrict__ pe,
                                   const float* __restrict__ lc) {
    int idx = blockIdx.x * blockDim.x + threadIdx.x;
    if (idx >= BINS * EMB) return;
    int p = idx / EMB;   // bin index 0..256
    int e = idx % EMB;   // embedding dim
    float v;
    if (e < HALF) {
        v = pe[(size_t)e * PLANE + p];                 // h = 0, w = p
    } else {
        v = pe[(size_t)e * PLANE + (size_t)p * BINS];  // h = p, w = 0
    }
    g_table[idx] = v + lc[e];   // coalesced write (e fastest)
}

// ---------------------------------------------------------------------------
// Exact digitize: idx = #{k : positions[k] <= x}, positions[k] = -5 + k*(5/128).
// All bin edges are exactly representable in fp32 (5*(k-128)/128, |mantissa|
// fits), and fmaf(k, 0.0390625f, -5.0f) computes them exactly, so the
// guess+fixup below reproduces jnp.searchsorted(..., side='right') exactly.
// After the clip, x in [-5, 5-1e-6] -> idx in [1, 256].
// ---------------------------------------------------------------------------
__device__ __forceinline__ int digitize256(float x) {
    float xc = fminf(fmaxf(x, -5.0f), 5.0f - 1e-6f);
    int k = (int)floorf((xc + 5.0f) * 25.6f);   // initial guess
    k = max(0, min(k, 255));
    // fix up (at most a step or two; edges computed exactly)
    while (k < 255 && fmaf((float)(k + 1), 0.0390625f, -5.0f) <= xc) k++;
    while (k > 0   && fmaf((float)k,       0.0390625f, -5.0f) >  xc) k--;
    return k + 1;
}

// ---------------------------------------------------------------------------
// Kernel B: one warp copies one 6 KB output row at a time.
//   out[i, e] = T[(e < 768 ? idx2 : idx1)][e]
// Row read: two contiguous 3 KB segments from the L2-resident table
// (LDG.128, fully coalesced). Row write: contiguous 6 KB (STG.128, coalesced).
// Block = 256 threads (8 warps); each block owns 32 consecutive rows,
// warp w handles rows {base+w, base+w+8, base+w+16, base+w+24}.
// ---------------------------------------------------------------------------
__global__ void __launch_bounds__(256)
row_copy_kernel(const float* __restrict__ x1,
                const float* __restrict__ x2,
                float4* __restrict__ out) {
    const float4* __restrict__ tab = reinterpret_cast<const float4*>(g_table);
    const int warp = threadIdx.x >> 5;
    const int lane = threadIdx.x & 31;
    const int row0 = blockIdx.x * 32 + warp;

    #pragma unroll
    for (int r = 0; r < 4; r++) {
        const int row = row0 + r * 8;
        // All lanes load the same scalar (single-sector broadcast) and
        // redundantly compute the bin indices — cheaper than a shuffle dance.
        const int i1 = digitize256(x1[row]);
        const int i2 = digitize256(x2[row]);
        const float4* __restrict__ srcW = tab + (size_t)i2 * ROW_F4; // e <  768
        const float4* __restrict__ srcH = tab + (size_t)i1 * ROW_F4; // e >= 768
        float4* __restrict__ dst = out + (size_t)row * ROW_F4;

        #pragma unroll
        for (int k = 0; k < 12; k++) {
            const int e4 = k * 32 + lane;            // 0..383
            // k < 6 -> entire warp in first half; k >= 6 -> second half.
            const float4 v = (e4 < HALF_F4) ? srcW[e4] : srcH[e4];
            dst[e4] = v;
        }
    }
}

extern "C" void kernel_launch(void* const* d_in, const int* in_sizes, int n_in,
                              void* d_out, int out_size) {
    const float* x1 = (const float*)d_in[0];
    const float* x2 = (const float*)d_in[1];
    const float* pe = (const float*)d_in[2];
    const float* lc = (const float*)d_in[3];
    float4* out = (float4*)d_out;

    // A: build factored table (394,752 elems; a few microseconds)
    build_table_kernel<<<(BINS * EMB + 255) / 256, 256>>>(pe, lc);

    // B: 65536 rows / 32 rows-per-block = 2048 blocks
    row_copy_kernel<<<N_SAMPLES / 32, 256>>>(x1, x2, out);
}